// round 13
// baseline (speedup 1.0000x reference)
#include <cuda_runtime.h>

#define VOL (1<<20)   // 32^4

// Wilson Dslash, DeGrand-Rossi basis, spin-projection form.
// psi: [V][4][3] re/im separate. U: [V][4][3][3] re/im separate.
// out: res_re at [0, V*12), res_im at [V*12, 2*V*12).
//
// Block = 256 consecutive sites = 8 full x3-rows; warp = one x3-row.
//  - psi staged in smem: mu=3 hops fully in-block, mu=2 hops in-block for
//    7 of 8 warps -> conflict-free LDS
//  - mu=3 U slices staged in smem (warp-local use)
//  - mu=0/mu=1 (and boundary mu=2) neighbor psi rows are WARP-UNIFORM
//    contiguous 1536B rows -> warp-cooperative dense LDG.128 + smem
//    transpose (24 wf vs 72 wf scattered), __syncwarp only
//  - U slices elsewhere: aligned vector loads (3 req / 9-float slice)

template<int MU, int FWD>
__device__ __forceinline__ void hop_core(const float vr[12], const float vi[12],
                                         const float* u_r, const float* u_i,
                                         float rr[12], float ri[12])
{
    // ---- spin projection ----
    float hr[6], hi[6];
#pragma unroll
    for (int c = 0; c < 3; ++c) {
        if (FWD) { // Pm = 1 - gamma_mu
            if (MU == 0) {
                hr[c]   = vr[c]   + vi[9+c]; hi[c]   = vi[c]   - vr[9+c];
                hr[3+c] = vr[3+c] + vi[6+c]; hi[3+c] = vi[3+c] - vr[6+c];
            } else if (MU == 1) {
                hr[c]   = vr[c]   + vr[9+c]; hi[c]   = vi[c]   + vi[9+c];
                hr[3+c] = vr[3+c] - vr[6+c]; hi[3+c] = vi[3+c] - vi[6+c];
            } else if (MU == 2) {
                hr[c]   = vr[c]   + vi[6+c]; hi[c]   = vi[c]   - vr[6+c];
                hr[3+c] = vr[3+c] - vi[9+c]; hi[3+c] = vi[3+c] + vr[9+c];
            } else {
                hr[c]   = vr[c]   - vr[6+c]; hi[c]   = vi[c]   - vi[6+c];
                hr[3+c] = vr[3+c] - vr[9+c]; hi[3+c] = vi[3+c] - vi[9+c];
            }
        } else { // Pp = 1 + gamma_mu
            if (MU == 0) {
                hr[c]   = vr[c]   - vi[9+c]; hi[c]   = vi[c]   + vr[9+c];
                hr[3+c] = vr[3+c] - vi[6+c]; hi[3+c] = vi[3+c] + vr[6+c];
            } else if (MU == 1) {
                hr[c]   = vr[c]   - vr[9+c]; hi[c]   = vi[c]   - vi[9+c];
                hr[3+c] = vr[3+c] + vr[6+c]; hi[3+c] = vi[3+c] + vi[6+c];
            } else if (MU == 2) {
                hr[c]   = vr[c]   - vi[6+c]; hi[c]   = vi[c]   + vr[6+c];
                hr[3+c] = vr[3+c] + vi[9+c]; hi[3+c] = vi[3+c] - vr[9+c];
            } else {
                hr[c]   = vr[c]   + vr[6+c]; hi[c]   = vi[c]   + vi[6+c];
                hr[3+c] = vr[3+c] + vr[9+c]; hi[3+c] = vi[3+c] + vi[9+c];
            }
        }
    }

    // ---- color multiply: a = U h (fwd) or U^dag h (bwd) ----
    float ar[6] = {0,0,0,0,0,0}, ai[6] = {0,0,0,0,0,0};
#pragma unroll
    for (int i = 0; i < 3; ++i) {
#pragma unroll
        for (int j = 0; j < 3; ++j) {
            float urr = FWD ? u_r[i*3 + j] :  u_r[j*3 + i];
            float uii = FWD ? u_i[i*3 + j] : -u_i[j*3 + i];
            ar[i]   += urr*hr[j]   - uii*hi[j];
            ai[i]   += urr*hi[j]   + uii*hr[j];
            ar[3+i] += urr*hr[3+j] - uii*hi[3+j];
            ai[3+i] += urr*hi[3+j] + uii*hr[3+j];
        }
    }

    // ---- reconstruct ----
#pragma unroll
    for (int c = 0; c < 3; ++c) {
        rr[c]   += ar[c];   ri[c]   += ai[c];
        rr[3+c] += ar[3+c]; ri[3+c] += ai[3+c];
        if (FWD) {
            if (MU == 0) {
                rr[6+c] -= ai[3+c]; ri[6+c] += ar[3+c];
                rr[9+c] -= ai[c];   ri[9+c] += ar[c];
            } else if (MU == 1) {
                rr[6+c] -= ar[3+c]; ri[6+c] -= ai[3+c];
                rr[9+c] += ar[c];   ri[9+c] += ai[c];
            } else if (MU == 2) {
                rr[6+c] -= ai[c];   ri[6+c] += ar[c];
                rr[9+c] += ai[3+c]; ri[9+c] -= ar[3+c];
            } else {
                rr[6+c] -= ar[c];   ri[6+c] -= ai[c];
                rr[9+c] -= ar[3+c]; ri[9+c] -= ai[3+c];
            }
        } else {
            if (MU == 0) {
                rr[6+c] += ai[3+c]; ri[6+c] -= ar[3+c];
                rr[9+c] += ai[c];   ri[9+c] -= ar[c];
            } else if (MU == 1) {
                rr[6+c] += ar[3+c]; ri[6+c] += ai[3+c];
                rr[9+c] -= ar[c];   ri[9+c] -= ai[c];
            } else if (MU == 2) {
                rr[6+c] += ai[c];   ri[6+c] -= ar[c];
                rr[9+c] -= ai[3+c]; ri[9+c] += ar[3+c];
            } else {
                rr[6+c] += ar[c];   ri[6+c] += ai[c];
                rr[9+c] += ar[3+c]; ri[9+c] += ai[3+c];
            }
        }
    }
}

// Warp-cooperative load of a full x3-row's psi (row_base .. row_base+31),
// dense LDG.128 + smem transpose in a per-warp 192-float4 buffer.
// Lane L ends up with site (row_base + L)'s 12 re + 12 im floats.
__device__ __forceinline__ void load_psi_row_coop(int row_base, int lane,
                                                  const float* __restrict__ pr,
                                                  const float* __restrict__ pi,
                                                  float4* buf,
                                                  float vr[12], float vi[12])
{
    const float4* p4 = reinterpret_cast<const float4*>(pr + (size_t)row_base * 12);
    const float4* q4 = reinterpret_cast<const float4*>(pi + (size_t)row_base * 12);
    float4 a0 = __ldg(p4 + lane);
    float4 a1 = __ldg(p4 + lane + 32);
    float4 a2 = __ldg(p4 + lane + 64);
    float4 b0 = __ldg(q4 + lane);
    float4 b1 = __ldg(q4 + lane + 32);
    float4 b2 = __ldg(q4 + lane + 64);
    __syncwarp();                      // WAR: prior reads of buf complete
    buf[lane      ] = a0; buf[lane + 32] = a1; buf[lane + 64] = a2;
    buf[lane +  96] = b0; buf[lane +128] = b1; buf[lane +160] = b2;
    __syncwarp();
    float4 r0 = buf[3*lane], r1 = buf[3*lane+1], r2 = buf[3*lane+2];
    float4 s0 = buf[96+3*lane], s1 = buf[96+3*lane+1], s2 = buf[96+3*lane+2];
    vr[0]=r0.x; vr[1]=r0.y; vr[2]=r0.z; vr[3]=r0.w;
    vr[4]=r1.x; vr[5]=r1.y; vr[6]=r1.z; vr[7]=r1.w;
    vr[8]=r2.x; vr[9]=r2.y; vr[10]=r2.z; vr[11]=r2.w;
    vi[0]=s0.x; vi[1]=s0.y; vi[2]=s0.z; vi[3]=s0.w;
    vi[4]=s1.x; vi[5]=s1.y; vi[6]=s1.z; vi[7]=s1.w;
    vi[8]=s2.x; vi[9]=s2.y; vi[10]=s2.z; vi[11]=s2.w;
}

// Vector-load the 9-float U slice for direction MU at site s (base float index
// s*36 + MU*9) using only aligned float4/float2/float requests.
template<int MU>
__device__ __forceinline__ void load_slice(const float* __restrict__ U, int s, float u[9])
{
    const float* p = U + (size_t)s * 36;   // 144B block, 16B aligned
    if (MU == 0) {
        float4 a = __ldg(reinterpret_cast<const float4*>(p));
        float4 b = __ldg(reinterpret_cast<const float4*>(p) + 1);
        float  c = __ldg(p + 8);
        u[0]=a.x; u[1]=a.y; u[2]=a.z; u[3]=a.w;
        u[4]=b.x; u[5]=b.y; u[6]=b.z; u[7]=b.w; u[8]=c;
    } else if (MU == 1) {
        float4 a = __ldg(reinterpret_cast<const float4*>(p + 8));
        float4 b = __ldg(reinterpret_cast<const float4*>(p + 12));
        float2 c = __ldg(reinterpret_cast<const float2*>(p + 16));
        u[0]=a.y; u[1]=a.z; u[2]=a.w;
        u[3]=b.x; u[4]=b.y; u[5]=b.z; u[6]=b.w;
        u[7]=c.x; u[8]=c.y;
    } else if (MU == 2) {
        float4 a = __ldg(reinterpret_cast<const float4*>(p + 16));
        float4 b = __ldg(reinterpret_cast<const float4*>(p + 20));
        float4 c = __ldg(reinterpret_cast<const float4*>(p + 24));
        u[0]=a.z; u[1]=a.w;
        u[2]=b.x; u[3]=b.y; u[4]=b.z; u[5]=b.w;
        u[6]=c.x; u[7]=c.y; u[8]=c.z;
    } else {
        float  a = __ldg(p + 27);
        float4 b = __ldg(reinterpret_cast<const float4*>(p + 28));
        float4 c = __ldg(reinterpret_cast<const float4*>(p + 32));
        u[0]=a;
        u[1]=b.x; u[2]=b.y; u[3]=b.z; u[4]=b.w;
        u[5]=c.x; u[6]=c.y; u[7]=c.z; u[8]=c.w;
    }
}

#define SMEM_BYTES 67584   // 24KB psi + 18KB U3 + 24KB warp transpose buffers

__global__ void __launch_bounds__(256, 3)
dslash_kernel(const float* __restrict__ psi_re, const float* __restrict__ psi_im,
              const float* __restrict__ U_re,  const float* __restrict__ U_im,
              float* __restrict__ out_re, float* __restrict__ out_im)
{
    extern __shared__ float smem[];
    float* spr = smem;                 // [12][256]
    float* spi = spr + 12*256;         // [12][256]
    float* s3r = spi + 12*256;         // [9][256]
    float* s3i = s3r + 9*256;          // [9][256]
    float4* sbuf = reinterpret_cast<float4*>(s3i + 9*256);  // [8][192] float4

    int tid  = threadIdx.x;
    int base = blockIdx.x * 256;
    int site = base + tid;

    int x3 =  tid         & 31;   // lane = x3 within the warp's row
    int wrp =  tid >> 5;          // local x2 (warp id)
    int x2 = (site >> 5)  & 31;
    int x1 = (site >> 10) & 31;
    int x0 = (site >> 15) & 31;

    const int S0 = 32768, S1 = 1024, S2 = 32;

    int fw0 = (x0 < 31) ? site + S0 : site - 31*S0;
    int bw0 = (x0 > 0)  ? site - S0 : site + 31*S0;
    int fw1 = (x1 < 31) ? site + S1 : site - 31*S1;
    int bw1 = (x1 > 0)  ? site - S1 : site + 31*S1;
    int fw2 = (x2 < 31) ? site + S2 : site - 31*S2;
    int bw2 = (x2 > 0)  ? site - S2 : site + 31*S2;

    float4* mybuf = sbuf + wrp * 192;

    // ---- publish own psi + own mu=3 U slice to smem ----
    {
        const float4* p4 = reinterpret_cast<const float4*>(psi_re + (size_t)site * 12);
        const float4* q4 = reinterpret_cast<const float4*>(psi_im + (size_t)site * 12);
#pragma unroll
        for (int k = 0; k < 3; ++k) {
            float4 a = __ldg(p4 + k);
            spr[(4*k+0)*256 + tid] = a.x; spr[(4*k+1)*256 + tid] = a.y;
            spr[(4*k+2)*256 + tid] = a.z; spr[(4*k+3)*256 + tid] = a.w;
            float4 b = __ldg(q4 + k);
            spi[(4*k+0)*256 + tid] = b.x; spi[(4*k+1)*256 + tid] = b.y;
            spi[(4*k+2)*256 + tid] = b.z; spi[(4*k+3)*256 + tid] = b.w;
        }
        float ut[9];
        load_slice<3>(U_re, site, ut);
#pragma unroll
        for (int j = 0; j < 9; ++j) s3r[j*256 + tid] = ut[j];
        load_slice<3>(U_im, site, ut);
#pragma unroll
        for (int j = 0; j < 9; ++j) s3i[j*256 + tid] = ut[j];
    }
    __syncthreads();

    float rr[12], ri[12];
#pragma unroll
    for (int k = 0; k < 12; ++k) { rr[k] = 0.f; ri[k] = 0.f; }

    float vr[12], vi[12], uar[9], uai[9];

    // ---- mu=3 forward: psi + U from smem (warp-local) ----
    {
        int nt = (x3 < 31) ? tid + 1 : tid - 31;
#pragma unroll
        for (int k = 0; k < 12; ++k) { vr[k] = spr[k*256 + nt]; vi[k] = spi[k*256 + nt]; }
#pragma unroll
        for (int j = 0; j < 9; ++j) { uar[j] = s3r[j*256 + tid]; uai[j] = s3i[j*256 + tid]; }
        hop_core<3,1>(vr, vi, uar, uai, rr, ri);
    }
    // ---- mu=3 backward: psi + U from smem (warp-local) ----
    {
        int nt = (x3 > 0) ? tid - 1 : tid + 31;
#pragma unroll
        for (int k = 0; k < 12; ++k) { vr[k] = spr[k*256 + nt]; vi[k] = spi[k*256 + nt]; }
#pragma unroll
        for (int j = 0; j < 9; ++j) { uar[j] = s3r[j*256 + nt]; uai[j] = s3i[j*256 + nt]; }
        hop_core<3,0>(vr, vi, uar, uai, rr, ri);
    }

    // ---- mu=2 forward: psi smem for warps 0..6, coop row load for warp 7 ----
    {
        if (wrp < 7) {
            int nt = tid + 32;
#pragma unroll
            for (int k = 0; k < 12; ++k) { vr[k] = spr[k*256 + nt]; vi[k] = spi[k*256 + nt]; }
        } else {
            load_psi_row_coop(fw2 & ~31, x3, psi_re, psi_im, mybuf, vr, vi);
        }
        load_slice<2>(U_re, site, uar);
        load_slice<2>(U_im, site, uai);
        hop_core<2,1>(vr, vi, uar, uai, rr, ri);
    }
    // ---- mu=2 backward: psi smem for warps 1..7, coop row load for warp 0 ----
    {
        if (wrp > 0) {
            int nt = tid - 32;
#pragma unroll
            for (int k = 0; k < 12; ++k) { vr[k] = spr[k*256 + nt]; vi[k] = spi[k*256 + nt]; }
        } else {
            load_psi_row_coop(bw2 & ~31, x3, psi_re, psi_im, mybuf, vr, vi);
        }
        load_slice<2>(U_re, bw2, uar);   // L1 hit for warps 1..7 (loaded by tid-32)
        load_slice<2>(U_im, bw2, uai);
        hop_core<2,0>(vr, vi, uar, uai, rr, ri);
    }

    // ---- mu=1 forward / backward: warp-cooperative dense psi rows ----
    {
        load_psi_row_coop(fw1 & ~31, x3, psi_re, psi_im, mybuf, vr, vi);
        load_slice<1>(U_re, site, uar);
        load_slice<1>(U_im, site, uai);
        hop_core<1,1>(vr, vi, uar, uai, rr, ri);
    }
    {
        load_psi_row_coop(bw1 & ~31, x3, psi_re, psi_im, mybuf, vr, vi);
        load_slice<1>(U_re, bw1, uar);
        load_slice<1>(U_im, bw1, uai);
        hop_core<1,0>(vr, vi, uar, uai, rr, ri);
    }

    // ---- mu=0 forward / backward: warp-cooperative dense psi rows ----
    {
        load_psi_row_coop(fw0 & ~31, x3, psi_re, psi_im, mybuf, vr, vi);
        load_slice<0>(U_re, site, uar);
        load_slice<0>(U_im, site, uai);
        hop_core<0,1>(vr, vi, uar, uai, rr, ri);
    }
    {
        load_psi_row_coop(bw0 & ~31, x3, psi_re, psi_im, mybuf, vr, vi);
        load_slice<0>(U_re, bw0, uar);
        load_slice<0>(U_im, bw0, uai);
        hop_core<0,0>(vr, vi, uar, uai, rr, ri);
    }

    // ---- store: res = -0.5 * accum ----
    float4* o4r = reinterpret_cast<float4*>(out_re + (size_t)site * 12);
    float4* o4i = reinterpret_cast<float4*>(out_im + (size_t)site * 12);
    float4 t;
    t.x = -0.5f*rr[0]; t.y = -0.5f*rr[1]; t.z = -0.5f*rr[2];  t.w = -0.5f*rr[3];  o4r[0] = t;
    t.x = -0.5f*rr[4]; t.y = -0.5f*rr[5]; t.z = -0.5f*rr[6];  t.w = -0.5f*rr[7];  o4r[1] = t;
    t.x = -0.5f*rr[8]; t.y = -0.5f*rr[9]; t.z = -0.5f*rr[10]; t.w = -0.5f*rr[11]; o4r[2] = t;
    t.x = -0.5f*ri[0]; t.y = -0.5f*ri[1]; t.z = -0.5f*ri[2];  t.w = -0.5f*ri[3];  o4i[0] = t;
    t.x = -0.5f*ri[4]; t.y = -0.5f*ri[5]; t.z = -0.5f*ri[6];  t.w = -0.5f*ri[7];  o4i[1] = t;
    t.x = -0.5f*ri[8]; t.y = -0.5f*ri[9]; t.z = -0.5f*ri[10]; t.w = -0.5f*ri[11]; o4i[2] = t;
}

extern "C" void kernel_launch(void* const* d_in, const int* in_sizes, int n_in,
                              void* d_out, int out_size)
{
    const float* psi_re = (const float*)d_in[0];
    const float* psi_im = (const float*)d_in[1];
    const float* U_re   = (const float*)d_in[2];
    const float* U_im   = (const float*)d_in[3];
    // d_in[4..7] are the fixed DeGrand-Rossi projectors; algebra is hardcoded.

    float* out_re = (float*)d_out;
    float* out_im = out_re + (size_t)VOL * 12;

    cudaFuncSetAttribute(dslash_kernel,
                         cudaFuncAttributeMaxDynamicSharedMemorySize, SMEM_BYTES);
    dslash_kernel<<<VOL / 256, 256, SMEM_BYTES>>>(psi_re, psi_im, U_re, U_im,
                                                  out_re, out_im);
}

// round 14
// speedup vs baseline: 2.2489x; 2.2489x over previous
#include <cuda_runtime.h>

#define VOL (1<<20)   // 32^4

// Wilson Dslash, DeGrand-Rossi basis, spin-projection form.
// psi: [V][4][3] re/im separate. U: [V][4][3][3] re/im separate.
// out: res_re at [0, V*12), res_im at [V*12, 2*V*12).
//
// Block = 256 consecutive sites = 8 full x3-rows (R6 structure).
//  - psi staged in smem SITE-MAJOR via cp.async (6x16B per thread, no
//    register round-trip, no transpose stores); LDS.128 reads are
//    conflict-free (stride 12 words -> 8 distinct bank groups per phase)
//  - mu=3 U slices staged site-major (stride 9: conflict-free)
//  - mu=3 hops fully in-block; mu=2 hops in-block for 7 of 8 warps
//  - remaining U reads: aligned vector loads (3 req / 9-float slice)

__device__ __forceinline__ unsigned smem_u32(const void* p) {
    unsigned a;
    asm("{ .reg .u64 t; cvta.to.shared.u64 t, %1; cvt.u32.u64 %0, t; }"
        : "=r"(a) : "l"(p));
    return a;
}

template<int MU, int FWD>
__device__ __forceinline__ void hop_core(const float vr[12], const float vi[12],
                                         const float* u_r, const float* u_i,
                                         float rr[12], float ri[12])
{
    // ---- spin projection ----
    float hr[6], hi[6];
#pragma unroll
    for (int c = 0; c < 3; ++c) {
        if (FWD) { // Pm = 1 - gamma_mu
            if (MU == 0) {
                hr[c]   = vr[c]   + vi[9+c]; hi[c]   = vi[c]   - vr[9+c];
                hr[3+c] = vr[3+c] + vi[6+c]; hi[3+c] = vi[3+c] - vr[6+c];
            } else if (MU == 1) {
                hr[c]   = vr[c]   + vr[9+c]; hi[c]   = vi[c]   + vi[9+c];
                hr[3+c] = vr[3+c] - vr[6+c]; hi[3+c] = vi[3+c] - vi[6+c];
            } else if (MU == 2) {
                hr[c]   = vr[c]   + vi[6+c]; hi[c]   = vi[c]   - vr[6+c];
                hr[3+c] = vr[3+c] - vi[9+c]; hi[3+c] = vi[3+c] + vr[9+c];
            } else {
                hr[c]   = vr[c]   - vr[6+c]; hi[c]   = vi[c]   - vi[6+c];
                hr[3+c] = vr[3+c] - vr[9+c]; hi[3+c] = vi[3+c] - vi[9+c];
            }
        } else { // Pp = 1 + gamma_mu
            if (MU == 0) {
                hr[c]   = vr[c]   - vi[9+c]; hi[c]   = vi[c]   + vr[9+c];
                hr[3+c] = vr[3+c] - vi[6+c]; hi[3+c] = vi[3+c] + vr[6+c];
            } else if (MU == 1) {
                hr[c]   = vr[c]   - vr[9+c]; hi[c]   = vi[c]   - vi[9+c];
                hr[3+c] = vr[3+c] + vr[6+c]; hi[3+c] = vi[3+c] + vi[6+c];
            } else if (MU == 2) {
                hr[c]   = vr[c]   - vi[6+c]; hi[c]   = vi[c]   + vr[6+c];
                hr[3+c] = vr[3+c] + vi[9+c]; hi[3+c] = vi[3+c] - vr[9+c];
            } else {
                hr[c]   = vr[c]   + vr[6+c]; hi[c]   = vi[c]   + vi[6+c];
                hr[3+c] = vr[3+c] + vr[9+c]; hi[3+c] = vi[3+c] + vi[9+c];
            }
        }
    }

    // ---- color multiply: a = U h (fwd) or U^dag h (bwd) ----
    float ar[6] = {0,0,0,0,0,0}, ai[6] = {0,0,0,0,0,0};
#pragma unroll
    for (int i = 0; i < 3; ++i) {
#pragma unroll
        for (int j = 0; j < 3; ++j) {
            float urr = FWD ? u_r[i*3 + j] :  u_r[j*3 + i];
            float uii = FWD ? u_i[i*3 + j] : -u_i[j*3 + i];
            ar[i]   += urr*hr[j]   - uii*hi[j];
            ai[i]   += urr*hi[j]   + uii*hr[j];
            ar[3+i] += urr*hr[3+j] - uii*hi[3+j];
            ai[3+i] += urr*hi[3+j] + uii*hr[3+j];
        }
    }

    // ---- reconstruct ----
#pragma unroll
    for (int c = 0; c < 3; ++c) {
        rr[c]   += ar[c];   ri[c]   += ai[c];
        rr[3+c] += ar[3+c]; ri[3+c] += ai[3+c];
        if (FWD) {
            if (MU == 0) {
                rr[6+c] -= ai[3+c]; ri[6+c] += ar[3+c];
                rr[9+c] -= ai[c];   ri[9+c] += ar[c];
            } else if (MU == 1) {
                rr[6+c] -= ar[3+c]; ri[6+c] -= ai[3+c];
                rr[9+c] += ar[c];   ri[9+c] += ai[c];
            } else if (MU == 2) {
                rr[6+c] -= ai[c];   ri[6+c] += ar[c];
                rr[9+c] += ai[3+c]; ri[9+c] -= ar[3+c];
            } else {
                rr[6+c] -= ar[c];   ri[6+c] -= ai[c];
                rr[9+c] -= ar[3+c]; ri[9+c] -= ai[3+c];
            }
        } else {
            if (MU == 0) {
                rr[6+c] += ai[3+c]; ri[6+c] -= ar[3+c];
                rr[9+c] += ai[c];   ri[9+c] -= ar[c];
            } else if (MU == 1) {
                rr[6+c] += ar[3+c]; ri[6+c] += ai[3+c];
                rr[9+c] -= ar[c];   ri[9+c] -= ai[c];
            } else if (MU == 2) {
                rr[6+c] += ai[c];   ri[6+c] -= ar[c];
                rr[9+c] -= ai[3+c]; ri[9+c] += ar[3+c];
            } else {
                rr[6+c] += ar[c];   ri[6+c] += ai[c];
                rr[9+c] += ar[3+c]; ri[9+c] += ai[3+c];
            }
        }
    }
}

__device__ __forceinline__ void load_psi_global(int nbr,
                                                const float* __restrict__ pr,
                                                const float* __restrict__ pi,
                                                float vr[12], float vi[12])
{
    const float4* p4 = reinterpret_cast<const float4*>(pr + (size_t)nbr * 12);
    float4 a = __ldg(p4 + 0), b = __ldg(p4 + 1), c = __ldg(p4 + 2);
    vr[0]=a.x; vr[1]=a.y; vr[2]=a.z; vr[3]=a.w;
    vr[4]=b.x; vr[5]=b.y; vr[6]=b.z; vr[7]=b.w;
    vr[8]=c.x; vr[9]=c.y; vr[10]=c.z; vr[11]=c.w;
    const float4* q4 = reinterpret_cast<const float4*>(pi + (size_t)nbr * 12);
    a = __ldg(q4 + 0); b = __ldg(q4 + 1); c = __ldg(q4 + 2);
    vi[0]=a.x; vi[1]=a.y; vi[2]=a.z; vi[3]=a.w;
    vi[4]=b.x; vi[5]=b.y; vi[6]=b.z; vi[7]=b.w;
    vi[8]=c.x; vi[9]=c.y; vi[10]=c.z; vi[11]=c.w;
}

// Vector-load the 9-float U slice for direction MU at site s (base float index
// s*36 + MU*9) using only aligned float4/float2/float requests.
template<int MU>
__device__ __forceinline__ void load_slice(const float* __restrict__ U, int s, float u[9])
{
    const float* p = U + (size_t)s * 36;   // 144B block, 16B aligned
    if (MU == 0) {
        float4 a = __ldg(reinterpret_cast<const float4*>(p));
        float4 b = __ldg(reinterpret_cast<const float4*>(p) + 1);
        float  c = __ldg(p + 8);
        u[0]=a.x; u[1]=a.y; u[2]=a.z; u[3]=a.w;
        u[4]=b.x; u[5]=b.y; u[6]=b.z; u[7]=b.w; u[8]=c;
    } else if (MU == 1) {
        float4 a = __ldg(reinterpret_cast<const float4*>(p + 8));
        float4 b = __ldg(reinterpret_cast<const float4*>(p + 12));
        float2 c = __ldg(reinterpret_cast<const float2*>(p + 16));
        u[0]=a.y; u[1]=a.z; u[2]=a.w;
        u[3]=b.x; u[4]=b.y; u[5]=b.z; u[6]=b.w;
        u[7]=c.x; u[8]=c.y;
    } else if (MU == 2) {
        float4 a = __ldg(reinterpret_cast<const float4*>(p + 16));
        float4 b = __ldg(reinterpret_cast<const float4*>(p + 20));
        float4 c = __ldg(reinterpret_cast<const float4*>(p + 24));
        u[0]=a.z; u[1]=a.w;
        u[2]=b.x; u[3]=b.y; u[4]=b.z; u[5]=b.w;
        u[6]=c.x; u[7]=c.y; u[8]=c.z;
    } else {
        float  a = __ldg(p + 27);
        float4 b = __ldg(reinterpret_cast<const float4*>(p + 28));
        float4 c = __ldg(reinterpret_cast<const float4*>(p + 32));
        u[0]=a;
        u[1]=b.x; u[2]=b.y; u[3]=b.z; u[4]=b.w;
        u[5]=c.x; u[6]=c.y; u[7]=c.z; u[8]=c.w;
    }
}

__global__ void __launch_bounds__(256, 3)
dslash_kernel(const float* __restrict__ psi_re, const float* __restrict__ psi_im,
              const float* __restrict__ U_re,  const float* __restrict__ U_im,
              float* __restrict__ out_re, float* __restrict__ out_im)
{
    // psi site-major: site s -> words [s*12, s*12+12)
    __shared__ float spr[256 * 12], spi[256 * 12];
    // mu=3 U slices site-major: site s -> words [s*9, s*9+9)
    __shared__ float s3r[256 * 9], s3i[256 * 9];

    int tid  = threadIdx.x;
    int base = blockIdx.x * 256;
    int site = base + tid;

    int x3 =  tid         & 31;   // lane = x3 within the warp's row
    int wrp =  tid >> 5;          // local x2 (warp id)
    int x2 = (site >> 5)  & 31;
    int x1 = (site >> 10) & 31;
    int x0 = (site >> 15) & 31;

    const int S0 = 32768, S1 = 1024, S2 = 32;

    int fw0 = (x0 < 31) ? site + S0 : site - 31*S0;
    int bw0 = (x0 > 0)  ? site - S0 : site + 31*S0;
    int fw1 = (x1 < 31) ? site + S1 : site - 31*S1;
    int bw1 = (x1 > 0)  ? site - S1 : site + 31*S1;
    int fw2 = (x2 < 31) ? site + S2 : site - 31*S2;
    int bw2 = (x2 > 0)  ? site - S2 : site + 31*S2;

    // ---- stage own psi via cp.async (site-major, 6x16B, no reg round-trip) ----
    {
        unsigned dr = smem_u32(spr + tid * 12);
        unsigned di = smem_u32(spi + tid * 12);
        const float* sr = psi_re + (size_t)site * 12;
        const float* si = psi_im + (size_t)site * 12;
#pragma unroll
        for (int k = 0; k < 3; ++k) {
            asm volatile("cp.async.ca.shared.global [%0], [%1], 16;"
                         :: "r"(dr + 16u*k), "l"(sr + 4*k) : "memory");
            asm volatile("cp.async.ca.shared.global [%0], [%1], 16;"
                         :: "r"(di + 16u*k), "l"(si + 4*k) : "memory");
        }
        asm volatile("cp.async.commit_group;" ::: "memory");
    }
    // ---- stage own mu=3 U slice (register path, site-major stride 9) ----
    {
        float ut[9];
        load_slice<3>(U_re, site, ut);
#pragma unroll
        for (int j = 0; j < 9; ++j) s3r[tid * 9 + j] = ut[j];
        load_slice<3>(U_im, site, ut);
#pragma unroll
        for (int j = 0; j < 9; ++j) s3i[tid * 9 + j] = ut[j];
    }
    asm volatile("cp.async.wait_group 0;" ::: "memory");
    __syncthreads();

    float rr[12], ri[12];
#pragma unroll
    for (int k = 0; k < 12; ++k) { rr[k] = 0.f; ri[k] = 0.f; }

    float vr[12], vi[12], uar[9], uai[9];

    // site-major psi reader: 3x LDS.128 per array (conflict-free)
    auto read_psi_smem = [&](int nt, float* wr, float* wi) {
        const float4* r4 = reinterpret_cast<const float4*>(spr + nt * 12);
        const float4* i4 = reinterpret_cast<const float4*>(spi + nt * 12);
#pragma unroll
        for (int k = 0; k < 3; ++k) {
            float4 a = r4[k];
            wr[4*k+0]=a.x; wr[4*k+1]=a.y; wr[4*k+2]=a.z; wr[4*k+3]=a.w;
            float4 b = i4[k];
            wi[4*k+0]=b.x; wi[4*k+1]=b.y; wi[4*k+2]=b.z; wi[4*k+3]=b.w;
        }
    };

    // ---- mu=3 forward: psi + U from smem (in-block always) ----
    {
        int nt = (x3 < 31) ? tid + 1 : tid - 31;
        read_psi_smem(nt, vr, vi);
#pragma unroll
        for (int j = 0; j < 9; ++j) { uar[j] = s3r[tid*9 + j]; uai[j] = s3i[tid*9 + j]; }
        hop_core<3,1>(vr, vi, uar, uai, rr, ri);
    }
    // ---- mu=3 backward: psi + U from smem (in-block always) ----
    {
        int nt = (x3 > 0) ? tid - 1 : tid + 31;
        read_psi_smem(nt, vr, vi);
#pragma unroll
        for (int j = 0; j < 9; ++j) { uar[j] = s3r[nt*9 + j]; uai[j] = s3i[nt*9 + j]; }
        hop_core<3,0>(vr, vi, uar, uai, rr, ri);
    }

    // ---- mu=2 forward: psi smem for warps 0..6, global for warp 7 ----
    {
        if (wrp < 7) {
            read_psi_smem(tid + 32, vr, vi);
        } else {
            load_psi_global(fw2, psi_re, psi_im, vr, vi);
        }
        load_slice<2>(U_re, site, uar);
        load_slice<2>(U_im, site, uai);
        hop_core<2,1>(vr, vi, uar, uai, rr, ri);
    }
    // ---- mu=2 backward: psi smem for warps 1..7, global for warp 0 ----
    {
        if (wrp > 0) {
            read_psi_smem(tid - 32, vr, vi);
        } else {
            load_psi_global(bw2, psi_re, psi_im, vr, vi);
        }
        load_slice<2>(U_re, bw2, uar);   // L1 hit for warps 1..7 (loaded by tid-32)
        load_slice<2>(U_im, bw2, uai);
        hop_core<2,0>(vr, vi, uar, uai, rr, ri);
    }

    // ---- mu=1 forward / backward: global ----
    {
        load_psi_global(fw1, psi_re, psi_im, vr, vi);
        load_slice<1>(U_re, site, uar);
        load_slice<1>(U_im, site, uai);
        hop_core<1,1>(vr, vi, uar, uai, rr, ri);
    }
    {
        load_psi_global(bw1, psi_re, psi_im, vr, vi);
        load_slice<1>(U_re, bw1, uar);
        load_slice<1>(U_im, bw1, uai);
        hop_core<1,0>(vr, vi, uar, uai, rr, ri);
    }

    // ---- mu=0 forward / backward: global ----
    {
        load_psi_global(fw0, psi_re, psi_im, vr, vi);
        load_slice<0>(U_re, site, uar);
        load_slice<0>(U_im, site, uai);
        hop_core<0,1>(vr, vi, uar, uai, rr, ri);
    }
    {
        load_psi_global(bw0, psi_re, psi_im, vr, vi);
        load_slice<0>(U_re, bw0, uar);
        load_slice<0>(U_im, bw0, uai);
        hop_core<0,0>(vr, vi, uar, uai, rr, ri);
    }

    // ---- store: res = -0.5 * accum ----
    float4* o4r = reinterpret_cast<float4*>(out_re + (size_t)site * 12);
    float4* o4i = reinterpret_cast<float4*>(out_im + (size_t)site * 12);
    float4 t;
    t.x = -0.5f*rr[0]; t.y = -0.5f*rr[1]; t.z = -0.5f*rr[2];  t.w = -0.5f*rr[3];  o4r[0] = t;
    t.x = -0.5f*rr[4]; t.y = -0.5f*rr[5]; t.z = -0.5f*rr[6];  t.w = -0.5f*rr[7];  o4r[1] = t;
    t.x = -0.5f*rr[8]; t.y = -0.5f*rr[9]; t.z = -0.5f*rr[10]; t.w = -0.5f*rr[11]; o4r[2] = t;
    t.x = -0.5f*ri[0]; t.y = -0.5f*ri[1]; t.z = -0.5f*ri[2];  t.w = -0.5f*ri[3];  o4i[0] = t;
    t.x = -0.5f*ri[4]; t.y = -0.5f*ri[5]; t.z = -0.5f*ri[6];  t.w = -0.5f*ri[7];  o4i[1] = t;
    t.x = -0.5f*ri[8]; t.y = -0.5f*ri[9]; t.z = -0.5f*ri[10]; t.w = -0.5f*ri[11]; o4i[2] = t;
}

extern "C" void kernel_launch(void* const* d_in, const int* in_sizes, int n_in,
                              void* d_out, int out_size)
{
    const float* psi_re = (const float*)d_in[0];
    const float* psi_im = (const float*)d_in[1];
    const float* U_re   = (const float*)d_in[2];
    const float* U_im   = (const float*)d_in[3];
    // d_in[4..7] are the fixed DeGrand-Rossi projectors; algebra is hardcoded.

    float* out_re = (float*)d_out;
    float* out_im = out_re + (size_t)VOL * 12;

    dslash_kernel<<<VOL / 256, 256>>>(psi_re, psi_im, U_re, U_im, out_re, out_im);
}